// round 2
// baseline (speedup 1.0000x reference)
#include <cuda_runtime.h>

typedef unsigned long long ull;

#define THREADS 256
#define BM 64
#define BK 16
#define BU 32
#define AP (BM + 4)   // padded smem row to kill STS bank conflicts

#define DH 256
#define NLEAF 16384
#define DIN 300

// ---------- packed fp32x2 helpers (sm_103a FFMA2 path, PTX-only) ----------
__device__ __forceinline__ ull pack2(float x) {
    ull r; asm("mov.b64 %0, {%1, %1};" : "=l"(r) : "f"(x)); return r;
}
__device__ __forceinline__ float2 unpack2(ull v) {
    float2 r; asm("mov.b64 {%0, %1}, %2;" : "=f"(r.x), "=f"(r.y) : "l"(v)); return r;
}
__device__ __forceinline__ void ffma2(ull& d, ull a, ull b) {
    asm("fma.rn.f32x2 %0, %1, %2, %0;" : "+l"(d) : "l"(a), "l"(b));
}
__device__ __forceinline__ float sigf(float x) { return 1.0f / (1.0f + expf(-x)); }

// ---------- scratch (device globals: no allocation allowed) ----------
__device__ float g_hA[NLEAF * DH];
__device__ float g_cA[NLEAF * DH];
__device__ float g_hB[(NLEAF / 2) * DH];
__device__ float g_cB[(NLEAF / 2) * DH];
__device__ float g_hl[(NLEAF / 2) * DH];
__device__ float g_cl[(NLEAF / 2) * DH];
__device__ float g_rc[DH];   // root cell (unused output)

// =====================================================================
// Leaf: h,c for every leaf.  gx = emb[ids] @ Wx + bx ; gi,go,cpre = split
// c = sig(gi)*tanh(cpre) ; h = sig(go)*tanh(c)
// Block: 64 leaves x 32 hidden units (3 gate columns each).
// =====================================================================
__global__ void __launch_bounds__(THREADS)
leaf_kernel(const int* __restrict__ ids, const float* __restrict__ emb,
            const float* __restrict__ Wx, const float* __restrict__ bx)
{
    __shared__ float As[BK][AP];
    __shared__ float Bs[BK][3 * BU];
    __shared__ int rid[BM];

    const int tid = threadIdx.x;
    const int tx = tid & 15;
    const int ty = tid >> 4;
    const int m0 = blockIdx.x * BM;
    const int u0 = blockIdx.y * BU;

    if (tid < BM) rid[tid] = ids[m0 + tid];
    __syncthreads();

    ull acc[4][3];
#pragma unroll
    for (int r = 0; r < 4; r++)
#pragma unroll
        for (int g = 0; g < 3; g++) acc[r][g] = 0ull;

    for (int k0 = 0; k0 < DIN; k0 += BK) {
#pragma unroll
        for (int i = 0; i < 4; i++) {
            int e = tid + i * THREADS;
            int m = e >> 4;
            int k = e & 15;
            float v = 0.0f;
            if (k0 + k < DIN) v = emb[rid[m] * DIN + k0 + k];
            As[k][m] = v;
        }
#pragma unroll
        for (int i = 0; i < 6; i++) {
            int e = tid + i * THREADS;
            int c = e % 96;
            int k = e / 96;
            int g = c >> 5;
            int u = c & 31;
            float v = 0.0f;
            if (k0 + k < DIN) v = Wx[(k0 + k) * 768 + g * 256 + u0 + u];
            Bs[k][c] = v;
        }
        __syncthreads();
#pragma unroll
        for (int kk = 0; kk < BK; kk++) {
            float4 av = *reinterpret_cast<const float4*>(&As[kk][ty * 4]);
            ull a0 = pack2(av.x), a1 = pack2(av.y), a2 = pack2(av.z), a3 = pack2(av.w);
            ull b0 = *reinterpret_cast<const ull*>(&Bs[kk][tx * 2]);
            ull b1 = *reinterpret_cast<const ull*>(&Bs[kk][32 + tx * 2]);
            ull b2 = *reinterpret_cast<const ull*>(&Bs[kk][64 + tx * 2]);
            ffma2(acc[0][0], a0, b0); ffma2(acc[0][1], a0, b1); ffma2(acc[0][2], a0, b2);
            ffma2(acc[1][0], a1, b0); ffma2(acc[1][1], a1, b1); ffma2(acc[1][2], a1, b2);
            ffma2(acc[2][0], a2, b0); ffma2(acc[2][1], a2, b1); ffma2(acc[2][2], a2, b2);
            ffma2(acc[3][0], a3, b0); ffma2(acc[3][1], a3, b1); ffma2(acc[3][2], a3, b2);
        }
        __syncthreads();
    }

    const int u = u0 + tx * 2;
    const float2 bgi = make_float2(bx[u],       bx[u + 1]);
    const float2 bgo = make_float2(bx[256 + u], bx[256 + u + 1]);
    const float2 bcp = make_float2(bx[512 + u], bx[512 + u + 1]);
#pragma unroll
    for (int r = 0; r < 4; r++) {
        int row = m0 + ty * 4 + r;
        float2 gi = unpack2(acc[r][0]); gi.x += bgi.x; gi.y += bgi.y;
        float2 go = unpack2(acc[r][1]); go.x += bgo.x; go.y += bgo.y;
        float2 cp = unpack2(acc[r][2]); cp.x += bcp.x; cp.y += bcp.y;
        float cx = sigf(gi.x) * tanhf(cp.x);
        float cy = sigf(gi.y) * tanhf(cp.y);
        float hx = sigf(go.x) * tanhf(cx);
        float hy = sigf(go.y) * tanhf(cy);
        *reinterpret_cast<float2*>(&g_cA[row * DH + u]) = make_float2(cx, cy);
        *reinterpret_cast<float2*>(&g_hA[row * DH + u]) = make_float2(hx, hy);
    }
}

// =====================================================================
// Stage 1 per level: left child (sibling = None).
// g = h_even @ Wc + bc + bs ; need only gc (cols 256:512), go (512:768).
// cl = sig(gc)*c_even ; hl = sig(go)*tanh(cl)
// src: 0 -> read A buffers, 1 -> read B buffers.
// root_out != nullptr: write hl to root_out (root combine, Mout==1).
// =====================================================================
__global__ void __launch_bounds__(THREADS)
comb1_kernel(int src, const float* __restrict__ Wc,
             const float* __restrict__ bc, const float* __restrict__ bs,
             int Mout, float* __restrict__ root_out)
{
    const float* __restrict__ h_in = src ? g_hB : g_hA;
    const float* __restrict__ c_in = src ? g_cB : g_cA;
    float* __restrict__ hl_out = root_out ? root_out : g_hl;
    float* __restrict__ cl_out = root_out ? g_rc : g_cl;

    __shared__ float As[BK][AP];
    __shared__ float Bs[BK][2 * BU];

    const int tid = threadIdx.x;
    const int tx = tid & 15;
    const int ty = tid >> 4;
    const int m0 = blockIdx.x * BM;
    const int u0 = blockIdx.y * BU;

    ull acc[4][2];
#pragma unroll
    for (int r = 0; r < 4; r++) { acc[r][0] = 0ull; acc[r][1] = 0ull; }

    for (int k0 = 0; k0 < DH; k0 += BK) {
#pragma unroll
        for (int i = 0; i < 4; i++) {
            int e = tid + i * THREADS;
            int m = e >> 4;
            int k = e & 15;
            As[k][m] = (m0 + m < Mout) ? h_in[(2 * (m0 + m)) * DH + k0 + k] : 0.0f;
        }
#pragma unroll
        for (int i = 0; i < 4; i++) {
            int e = tid + i * THREADS;
            int c = e & 63;
            int k = e >> 6;
            int g = c >> 5;
            int u = c & 31;
            Bs[k][c] = Wc[(k0 + k) * 768 + 256 + g * 256 + u0 + u];
        }
        __syncthreads();
#pragma unroll
        for (int kk = 0; kk < BK; kk++) {
            float4 av = *reinterpret_cast<const float4*>(&As[kk][ty * 4]);
            ull a0 = pack2(av.x), a1 = pack2(av.y), a2 = pack2(av.z), a3 = pack2(av.w);
            ull b0 = *reinterpret_cast<const ull*>(&Bs[kk][tx * 2]);
            ull b1 = *reinterpret_cast<const ull*>(&Bs[kk][32 + tx * 2]);
            ffma2(acc[0][0], a0, b0); ffma2(acc[0][1], a0, b1);
            ffma2(acc[1][0], a1, b0); ffma2(acc[1][1], a1, b1);
            ffma2(acc[2][0], a2, b0); ffma2(acc[2][1], a2, b1);
            ffma2(acc[3][0], a3, b0); ffma2(acc[3][1], a3, b1);
        }
        __syncthreads();
    }

    const int u = u0 + tx * 2;
    const float2 bgc = make_float2(bc[256 + u] + bs[256 + u], bc[256 + u + 1] + bs[256 + u + 1]);
    const float2 bgo = make_float2(bc[512 + u] + bs[512 + u], bc[512 + u + 1] + bs[512 + u + 1]);
#pragma unroll
    for (int r = 0; r < 4; r++) {
        int row = m0 + ty * 4 + r;
        if (row < Mout) {
            float2 gc = unpack2(acc[r][0]); gc.x += bgc.x; gc.y += bgc.y;
            float2 go = unpack2(acc[r][1]); go.x += bgo.x; go.y += bgo.y;
            float2 cc = *reinterpret_cast<const float2*>(&c_in[(2 * row) * DH + u]);
            float clx = sigf(gc.x) * cc.x;
            float cly = sigf(gc.y) * cc.y;
            float hlx = sigf(go.x) * tanhf(clx);
            float hly = sigf(go.y) * tanhf(cly);
            *reinterpret_cast<float2*>(&cl_out[row * DH + u]) = make_float2(clx, cly);
            *reinterpret_cast<float2*>(&hl_out[row * DH + u]) = make_float2(hlx, hly);
        }
    }
}

// =====================================================================
// Stage 2 per level: right child with sibling = stage-1 output.
// g = h_odd @ Wc + hl @ Ws + bc + bs  (K = 512 via concatenation)
// c' = sig(gc)*c_odd + sig(gs)*cl ; h' = sig(go)*tanh(c')
// src: 0 -> read A / write B ; 1 -> read B / write A
// =====================================================================
__global__ void __launch_bounds__(THREADS)
comb2_kernel(int src, const float* __restrict__ Wc, const float* __restrict__ Ws,
             const float* __restrict__ bc, const float* __restrict__ bs, int Mout)
{
    const float* __restrict__ h_in = src ? g_hB : g_hA;
    const float* __restrict__ c_in = src ? g_cB : g_cA;
    float* __restrict__ h_out = src ? g_hA : g_hB;
    float* __restrict__ c_out = src ? g_cA : g_cB;

    __shared__ float As[BK][AP];
    __shared__ float Bs[BK][3 * BU];

    const int tid = threadIdx.x;
    const int tx = tid & 15;
    const int ty = tid >> 4;
    const int m0 = blockIdx.x * BM;
    const int u0 = blockIdx.y * BU;

    ull acc[4][3];
#pragma unroll
    for (int r = 0; r < 4; r++)
#pragma unroll
        for (int g = 0; g < 3; g++) acc[r][g] = 0ull;

    for (int k0 = 0; k0 < 2 * DH; k0 += BK) {
        const bool second = (k0 >= DH);
        const float* __restrict__ W = second ? Ws : Wc;
        const int kw = second ? (k0 - DH) : k0;
#pragma unroll
        for (int i = 0; i < 4; i++) {
            int e = tid + i * THREADS;
            int m = e >> 4;
            int k = e & 15;
            float v = 0.0f;
            if (m0 + m < Mout) {
                v = second ? g_hl[(m0 + m) * DH + kw + k]
                           : h_in[(2 * (m0 + m) + 1) * DH + k0 + k];
            }
            As[k][m] = v;
        }
#pragma unroll
        for (int i = 0; i < 6; i++) {
            int e = tid + i * THREADS;
            int c = e % 96;
            int k = e / 96;
            int g = c >> 5;
            int uu = c & 31;
            Bs[k][c] = W[(kw + k) * 768 + g * 256 + u0 + uu];
        }
        __syncthreads();
#pragma unroll
        for (int kk = 0; kk < BK; kk++) {
            float4 av = *reinterpret_cast<const float4*>(&As[kk][ty * 4]);
            ull a0 = pack2(av.x), a1 = pack2(av.y), a2 = pack2(av.z), a3 = pack2(av.w);
            ull b0 = *reinterpret_cast<const ull*>(&Bs[kk][tx * 2]);
            ull b1 = *reinterpret_cast<const ull*>(&Bs[kk][32 + tx * 2]);
            ull b2 = *reinterpret_cast<const ull*>(&Bs[kk][64 + tx * 2]);
            ffma2(acc[0][0], a0, b0); ffma2(acc[0][1], a0, b1); ffma2(acc[0][2], a0, b2);
            ffma2(acc[1][0], a1, b0); ffma2(acc[1][1], a1, b1); ffma2(acc[1][2], a1, b2);
            ffma2(acc[2][0], a2, b0); ffma2(acc[2][1], a2, b1); ffma2(acc[2][2], a2, b2);
            ffma2(acc[3][0], a3, b0); ffma2(acc[3][1], a3, b1); ffma2(acc[3][2], a3, b2);
        }
        __syncthreads();
    }

    const int u = u0 + tx * 2;
    const float2 bgs = make_float2(bc[u] + bs[u], bc[u + 1] + bs[u + 1]);
    const float2 bgc = make_float2(bc[256 + u] + bs[256 + u], bc[256 + u + 1] + bs[256 + u + 1]);
    const float2 bgo = make_float2(bc[512 + u] + bs[512 + u], bc[512 + u + 1] + bs[512 + u + 1]);
#pragma unroll
    for (int r = 0; r < 4; r++) {
        int row = m0 + ty * 4 + r;
        if (row < Mout) {
            float2 gs_ = unpack2(acc[r][0]); gs_.x += bgs.x; gs_.y += bgs.y;
            float2 gc  = unpack2(acc[r][1]); gc.x  += bgc.x; gc.y  += bgc.y;
            float2 go  = unpack2(acc[r][2]); go.x  += bgo.x; go.y  += bgo.y;
            float2 co = *reinterpret_cast<const float2*>(&c_in[(2 * row + 1) * DH + u]);
            float2 cs = *reinterpret_cast<const float2*>(&g_cl[row * DH + u]);
            float cnx = sigf(gc.x) * co.x + sigf(gs_.x) * cs.x;
            float cny = sigf(gc.y) * co.y + sigf(gs_.y) * cs.y;
            float hnx = sigf(go.x) * tanhf(cnx);
            float hny = sigf(go.y) * tanhf(cny);
            *reinterpret_cast<float2*>(&c_out[row * DH + u]) = make_float2(cnx, cny);
            *reinterpret_cast<float2*>(&h_out[row * DH + u]) = make_float2(hnx, hny);
        }
    }
}

// =====================================================================
extern "C" void kernel_launch(void* const* d_in, const int* in_sizes, int n_in,
                              void* d_out, int out_size)
{
    const int*   ids = (const int*)d_in[0];
    const float* emb = (const float*)d_in[1];
    const float* Wx  = (const float*)d_in[2];
    const float* bx  = (const float*)d_in[3];
    const float* Ws  = (const float*)d_in[4];
    const float* bs  = (const float*)d_in[5];
    const float* Wc  = (const float*)d_in[6];
    const float* bc  = (const float*)d_in[7];
    float* out = (float*)d_out;
    (void)in_sizes; (void)n_in; (void)out_size;

    leaf_kernel<<<dim3(NLEAF / BM, DH / BU), THREADS>>>(ids, emb, Wx, bx);

    int M = NLEAF;
    for (int l = 0; l < 14; l++) {
        int Mo = M >> 1;
        int src = l & 1;   // 0: read A (write B), 1: read B (write A)
        dim3 grid((Mo + BM - 1) / BM, DH / BU);
        comb1_kernel<<<grid, THREADS>>>(src, Wc, bc, bs, Mo, nullptr);
        comb2_kernel<<<grid, THREADS>>>(src, Wc, Ws, bc, bs, Mo);
        M = Mo;
    }
    // After 14 levels the single node sits in the A buffers (14 is even).
    comb1_kernel<<<dim3(1, DH / BU), THREADS>>>(0, Wc, bc, bs, 1, out);
}